// round 8
// baseline (speedup 1.0000x reference)
#include <cuda_runtime.h>

#define RAD   5
#define HI    256
#define WI    256
#define HWSZ  (HI * WI)

#define TX    32
#define TY    8
#define SW    (TX + 2 * RAD)   /* 42 */
#define SH    (TY + RAD)       /* 13 */
#define NTHR  128              /* 4 warps; each thread owns 2 vertically adjacent pixels */
#define MAXBLK 4096

typedef unsigned long long u64;

__device__ float    p_num[MAXBLK];
__device__ float    p_den[MAXBLK];
__device__ unsigned g_count = 0;

// Compile-time exp (Taylor; |x| <= ~0.7 at the evaluated points)
__host__ __device__ constexpr float cexp_c(double x) {
    double s = 1.0, t = 1.0;
    for (int i = 1; i < 24; ++i) { t *= x / (double)i; s += t; }
    return (float)s;
}

// ---- f32x2 packed helpers (sm_103a FFMA2 path, PTX-only) ----
__device__ __forceinline__ u64 pack2(float a, float b) {
    u64 r; asm("mov.b64 %0, {%1, %2};" : "=l"(r) : "f"(a), "f"(b)); return r;
}
__device__ __forceinline__ u64 bcast2(float a) {
    u64 r; asm("mov.b64 %0, {%1, %1};" : "=l"(r) : "f"(a)); return r;
}
__device__ __forceinline__ void unpack2(u64 v, float& a, float& b) {
    asm("mov.b64 {%0, %1}, %2;" : "=f"(a), "=f"(b) : "l"(v));
}
__device__ __forceinline__ u64 add2(u64 a, u64 b) {
    u64 r; asm("add.rn.f32x2 %0, %1, %2;" : "=l"(r) : "l"(a), "l"(b)); return r;
}
__device__ __forceinline__ u64 mul2(u64 a, u64 b) {
    u64 r; asm("mul.rn.f32x2 %0, %1, %2;" : "=l"(r) : "l"(a), "l"(b)); return r;
}
__device__ __forceinline__ u64 fma2(u64 a, u64 b, u64 c) {
    u64 r; asm("fma.rn.f32x2 %0, %1, %2, %3;" : "=l"(r) : "l"(a), "l"(b), "l"(c)); return r;
}
__device__ __forceinline__ float ex2f(float a) {
    float r; asm("ex2.approx.f32 %0, %1;" : "=f"(r) : "f"(a)); return r;
}

// One shared load at row-offset K_ (0..6), col-offset DX serves:
//   pixel0 (row 2wy)   as dy=K_    (valid forward if 1<=K_<=5, or K_==0&&DX>0)
//   pixel1 (row 2wy+1) as dy=K_-1  (valid forward if 2<=K_<=6, or K_==1&&DX>0)
template <int L>
struct Step2 {
    static __device__ __forceinline__ void run(const float4* __restrict__ sf,
                                               const float2* __restrict__ sm,
                                               int base0,
                                               u64 npx, u64 npy, u64 npz,
                                               float b0, float c0, float b1, float c1,
                                               u64& acc1, u64& acc2) {
        constexpr int K_ = L / 11;
        constexpr int DX = L % 11 - 5;
        constexpr bool LOADQ = (K_ > 0) || (DX > 0);
        constexpr bool P0 = LOADQ && (K_ >= 1 ? K_ <= 5 : true);
        constexpr bool P1 = (K_ >= 2) || (K_ == 1 && DX > 0);
        if constexpr (LOADQ) {
            constexpr float G0 = cexp_c(-(double)(DX * DX + K_ * K_) / 72.0);
            constexpr float G1 = cexp_c(-(double)(DX * DX + (K_ - 1) * (K_ - 1)) / 72.0);
            constexpr float A0 = P0 ? 0.9f * G0 : 0.0f;
            constexpr float B0 = P0 ? 0.1f * G0 : 0.0f;
            constexpr float A1 = P1 ? 0.9f * G1 : 0.0f;
            constexpr float B1 = P1 ? 0.1f * G1 : 0.0f;
            constexpr int SOFF = K_ * SW + DX;

            float4 fq = sf[base0 + SOFF];
            float2 mq = sm[base0 + SOFF];
            // packed distance: d_i = q - p_i  (p pre-negated, packed (p0,p1))
            u64 d0 = add2(bcast2(fq.x), npx);
            u64 d1 = add2(bcast2(fq.y), npy);
            u64 d2 = add2(bcast2(fq.z), npz);
            u64 s2 = mul2(d0, d0);
            s2 = fma2(d1, d1, s2);
            s2 = fma2(d2, d2, s2);
            float s0, s1;
            unpack2(s2, s0, s1);
            // exp(-50*s) = exp2(-72.1348*s); FMUL-imm + MUFU, scalar per half
            float e0 = ex2f(s0 * (-72.134752044448170f));
            float e1 = ex2f(s1 * (-72.134752044448170f));
            float K0 = fmaf(A0, e0, B0);            // FFMA-imm (0 if half invalid)
            float K1 = fmaf(A1, e1, B1);
            float w0 = fmaf(fq.w, c0, b0);          // b_p + b_q - 2 b_p b_q
            float w1 = fmaf(fq.w, c1, b1);
            u64 t01 = pack2(K0 * w0, K1 * w1);
            acc1 = fma2(t01, bcast2(mq.x), acc1);   // * ms_q
            acc2 = fma2(t01, bcast2(mq.y), acc2);   // * md_q
        }
    }
};

template <int L, int END>
struct Loop2 {
    static __device__ __forceinline__ void run(const float4* sf, const float2* sm, int base0,
                                               u64 npx, u64 npy, u64 npz,
                                               float b0, float c0, float b1, float c1,
                                               u64& acc1, u64& acc2) {
        Step2<L>::run(sf, sm, base0, npx, npy, npz, b0, c0, b1, c1, acc1, acc2);
        Loop2<L + 1, END>::run(sf, sm, base0, npx, npy, npz, b0, c0, b1, c1, acc1, acc2);
    }
};
template <int END>
struct Loop2<END, END> {
    static __device__ __forceinline__ void run(const float4*, const float2*, int,
                                               u64, u64, u64, float, float, float, float,
                                               u64&, u64&) {}
};

__global__ void __launch_bounds__(NTHR) k_fused(const float* __restrict__ x,
                                                const float* __restrict__ y,
                                                const float* __restrict__ msrc,
                                                const float* __restrict__ mdst,
                                                float* __restrict__ out,
                                                int nblk) {
    __shared__ float4 sf[SH * SW];
    __shared__ float2 sm[SH * SW];
    __shared__ float red[NTHR / 32];
    __shared__ float red2[NTHR / 32];
    __shared__ int   slast;

    const int tileX = blockIdx.x * TX;
    const int tileY = blockIdx.y * TY;
    const int n = blockIdx.z;
    const int tid = threadIdx.x;
    const int bid = (blockIdx.z * gridDim.y + blockIdx.y) * gridDim.x + blockIdx.x;
    const int nbase = n * HWSZ;
    const float* xb = x + (size_t)n * 3 * HWSZ;

    // Load tile + halo directly from global, computing features on the fly.
    for (int i = tid; i < SH * SW; i += NTHR) {
        int ly = i / SW;
        int lx = i - ly * SW;
        int gy = tileY + ly;
        int gx = tileX + lx - RAD;
        float4 f = make_float4(0.f, 0.f, 0.f, 0.f);
        float2 m = make_float2(0.f, 0.f);
        if (gx >= 0 && gx < WI && gy < HI) {
            int r  = gy * WI + gx;
            f.x = xb[r];
            f.y = xb[HWSZ + r];
            f.z = xb[2 * HWSZ + r];
            float yy = y[nbase + r];
            f.w = 1.0f / (1.0f + __expf(-yy));       // sigmoid
            float ms = msrc[nbase + r];
            if (!(ms == ms) || ms < 1.0f) ms = 0.0f; // NaN->0, <1 -> 0
            float md = mdst[nbase + r];
            if (!(md == md) || md < 1.0f) md = 0.0f;
            m = make_float2(ms, md);
        }
        sf[i] = f;
        sm[i] = m;
    }
    __syncthreads();

    const int tx = tid & 31;
    const int wy = tid >> 5;              // 0..3 — rows 2*wy and 2*wy+1

    const int base0 = (2 * wy) * SW + (tx + RAD);
    const int base1 = base0 + SW;
    float4 fp0 = sf[base0];
    float2 mp0 = sm[base0];
    float4 fp1 = sf[base1];
    float2 mp1 = sm[base1];
    float c0 = 1.0f - 2.0f * fp0.w;
    float c1 = 1.0f - 2.0f * fp1.w;
    u64 npx = pack2(-fp0.x, -fp1.x);
    u64 npy = pack2(-fp0.y, -fp1.y);
    u64 npz = pack2(-fp0.z, -fp1.z);
    u64 acc1 = 0ull, acc2 = 0ull;         // packed (p0, p1) accumulators
    Loop2<0, 77>::run(sf, sm, base0, npx, npy, npz,
                      fp0.w, c0, fp1.w, c1, acc1, acc2);
    float a10, a11, a20, a21;
    unpack2(acc1, a10, a11);
    unpack2(acc2, a20, a21);
    // unordered pair counted once, both orderings: md_p*Σt*ms_q + ms_p*Σt*md_q
    float total = mp0.y * a10 + mp0.x * a20 + mp1.y * a11 + mp1.x * a21;
    float den   = mp0.y + mp1.y;          // denom: binarized md over core pixels

    // block reduce num + den (4 warps)
    #pragma unroll
    for (int o = 16; o; o >>= 1) {
        total += __shfl_xor_sync(0xffffffffu, total, o);
        den   += __shfl_xor_sync(0xffffffffu, den, o);
    }
    if ((tid & 31) == 0) { red[tid >> 5] = total; red2[tid >> 5] = den; }
    __syncthreads();
    if (tid == 0) {
        float vn = 0.0f, vd = 0.0f;
        #pragma unroll
        for (int i = 0; i < NTHR / 32; ++i) { vn += red[i]; vd += red2[i]; }
        p_num[bid] = vn;
        p_den[bid] = vd;
        __threadfence();
        unsigned t = atomicAdd(&g_count, 1u);
        slast = (t == (unsigned)(nblk - 1));
    }
    __syncthreads();

    // Last block: reduce all partials, write result, reset counter.
    if (slast) {
        float vn = 0.0f, vd = 0.0f;
        for (int i = tid; i < nblk; i += NTHR) { vn += p_num[i]; vd += p_den[i]; }
        #pragma unroll
        for (int o = 16; o; o >>= 1) {
            vn += __shfl_xor_sync(0xffffffffu, vn, o);
            vd += __shfl_xor_sync(0xffffffffu, vd, o);
        }
        if ((tid & 31) == 0) { red[tid >> 5] = vn; red2[tid >> 5] = vd; }
        __syncthreads();
        if (tid == 0) {
            float fn = 0.0f, fd = 0.0f;
            #pragma unroll
            for (int i = 0; i < NTHR / 32; ++i) { fn += red[i]; fd += red2[i]; }
            out[0] = fn / fmaxf(fd, 1.0f);
            g_count = 0;    // reset for next graph replay (deterministic)
        }
    }
}

extern "C" void kernel_launch(void* const* d_in, const int* in_sizes, int n_in,
                              void* d_out, int out_size) {
    const float* x    = (const float*)d_in[0];
    const float* y    = (const float*)d_in[1];
    const float* msrc = (const float*)d_in[2];
    const float* mdst = (const float*)d_in[3];

    int NHW = in_sizes[1];          // y element count = N*H*W
    int N   = NHW / HWSZ;

    dim3 grid(WI / TX, HI / TY, N);
    int nblk = grid.x * grid.y * grid.z;
    k_fused<<<grid, NTHR>>>(x, y, msrc, mdst, (float*)d_out, nblk);
}